// round 16
// baseline (speedup 1.0000x reference)
#include <cuda_runtime.h>
#include <cuda_bf16.h>
#include <math.h>

#define BATCH   16384
#define ENCD    512
#define HD      256
#define GD      1024
#define TSTEPS  64
#define ROWS    32
#define NTHR    256
#define HROWB   528     // A row bytes (264 bf16)

#define AHI     0       // 32*528 = 16896
#define ALO     16896
#define BBUF    33792   // 2 x 32768
#define VOFF2   99328
#define UOFF2   103424
#define WREDO   107520
#define YO      108544
#define PARTO   108672
#define SMEMSZ  109184

__device__ float g_v[GD];
__device__ float g_u[GD];
// W_r split bf16 hi/lo, permuted + SW128-swizzled SMEM image.
// 32 chunks (p*8+kc) x 256 n'-rows x 128B row = [hi k32 | lo k32], unit-swizzled.
__device__ unsigned short g_wimg[32 * 16384];

__global__ void precompute_vu_kernel(const float* __restrict__ W_emb,
                                     const float* __restrict__ b_emb,
                                     const float* __restrict__ W_k,
                                     const float* __restrict__ b_lstm) {
    int j = blockIdx.x * blockDim.x + threadIdx.x;
    if (j < GD) {
        float v = 0.f, u = 0.f;
        #pragma unroll
        for (int d = 0; d < 32; ++d) {
            float wk = W_k[d * GD + j];
            v += W_emb[d] * wk;
            u += b_emb[d] * wk;
        }
        g_v[j] = v;
        g_u[j] = u + b_lstm[j];
    }
}

// n' = g*64 + w64 within chunk; original col n = g*256 + p*64 + w64.
// 128B row = 8 x 16B units: u<4 -> hi k-bytes [u*16 .. ), u>=4 -> lo.
// unit placed at (u ^ (r&7)) for conflict-free LDSM.
__global__ void precompute_wimg_kernel(const float* __restrict__ W_r) {
    int idx = blockIdx.x * blockDim.x + threadIdx.x;  // 65536
    int ti = idx >> 11;
    int r  = (idx >> 3) & 255;
    int u  = idx & 7;
    int p = ti >> 3, kc = ti & 7;
    int g = r >> 6, w64 = r & 63;
    int n = g * 256 + p * 64 + w64;
    unsigned short* dst = g_wimg + ti * 16384
                        + ((r * 128 + ((u ^ (r & 7)) << 4)) >> 1);
    #pragma unroll
    for (int e = 0; e < 8; ++e) {
        int k = kc * 32 + (u & 3) * 8 + e;
        float val = W_r[(size_t)k * GD + n];
        __nv_bfloat16 hi = __float2bfloat16(val);
        if (u < 4) dst[e] = __bfloat16_as_ushort(hi);
        else dst[e] = __bfloat16_as_ushort(
                 __float2bfloat16(val - __bfloat162float(hi)));
    }
}

__device__ __forceinline__ float sigmoidf_(float x) {
    return __fdividef(1.f, 1.f + __expf(-x));
}
__device__ __forceinline__ float tanh_fast(float x) {
    float e = __expf(-2.f * x);
    return __fdividef(1.f - e, 1.f + e);
}
__device__ __forceinline__ void cp16(void* dst, const void* src) {
    unsigned s = (unsigned)__cvta_generic_to_shared(dst);
    asm volatile("cp.async.cg.shared.global [%0], [%1], 16;" :: "r"(s), "l"(src));
}
__device__ __forceinline__ void ldm_x4(unsigned* r, unsigned addr) {
    asm volatile("ldmatrix.sync.aligned.m8n8.x4.shared.b16 {%0,%1,%2,%3}, [%4];"
                 : "=r"(r[0]), "=r"(r[1]), "=r"(r[2]), "=r"(r[3]) : "r"(addr));
}
__device__ __forceinline__ void mma_bf16(float* d, const unsigned* a, const unsigned* b) {
    asm volatile("mma.sync.aligned.m16n8k16.row.col.f32.bf16.bf16.f32 "
                 "{%0,%1,%2,%3}, {%4,%5,%6,%7}, {%8,%9}, {%0,%1,%2,%3};"
                 : "+f"(d[0]), "+f"(d[1]), "+f"(d[2]), "+f"(d[3])
                 : "r"(a[0]), "r"(a[1]), "r"(a[2]), "r"(a[3]), "r"(b[0]), "r"(b[1]));
}

// epilogue cell block for pass P: j,cp,rh unrolled; updates cst/hstash/yd
#define EPI(P) do {                                                            \
    float yp0_ = shy[r0], yp1_ = shy[r1];                                      \
    _Pragma("unroll")                                                          \
    for (int j = 0; j < 2; ++j)                                                \
        _Pragma("unroll")                                                      \
        for (int cp = 0; cp < 2; ++cp) {                                       \
            int hcol = (P) * 64 + cq * 16 + j * 8 + (l & 3) * 2 + cp;          \
            float vi = shv[hcol],          ui = shu[hcol];                     \
            float vf = shv[HD + hcol],     uf = shu[HD + hcol];                \
            float vc = shv[2 * HD + hcol], uc = shu[2 * HD + hcol];            \
            float vo = shv[3 * HD + hcol], uo = shu[3 * HD + hcol];            \
            float wr = shwred[hcol];                                           \
            _Pragma("unroll")                                                  \
            for (int rh = 0; rh < 2; ++rh) {                                   \
                float yy = rh ? yp1_ : yp0_;                                   \
                int di = rh * 2 + cp;                                          \
                float gi = acc[0][j][di] + yy * vi + ui;                       \
                float gf = acc[1][j][di] + yy * vf + uf;                       \
                float gc = acc[2][j][di] + yy * vc + uc;                       \
                float go = acc[3][j][di] + yy * vo + uo;                       \
                int ci = j * 4 + cp * 2 + rh;                                  \
                float cn = sigmoidf_(gf) * cst[(P)][ci]                        \
                         + sigmoidf_(gi) * tanh_fast(gc);                      \
                float hn = sigmoidf_(go) * tanh_fast(cn);                      \
                cst[(P)][ci] = cn;                                             \
                __nv_bfloat16 hb = __float2bfloat16(hn);                       \
                __nv_bfloat16 lb = __float2bfloat16(hn - __bfloat162float(hb));\
                hstash[(P)][ci] = (unsigned)__bfloat16_as_ushort(hb)           \
                                | ((unsigned)__bfloat16_as_ushort(lb) << 16);  \
                if (rh) yd1 += hn * wr; else yd0 += hn * wr;                   \
            }                                                                  \
        }                                                                      \
} while (0)

__global__ void __launch_bounds__(NTHR, 2)
lstm_decode_kernel(const float* __restrict__ enc,
                   const float* __restrict__ finalx,
                   const float* __restrict__ W_enc,
                   const float* __restrict__ b_enc,
                   const float* __restrict__ W_red,
                   const float* __restrict__ b_red,
                   float* __restrict__ out)
{
    extern __shared__ char smem[];
    float* shv    = (float*)(smem + VOFF2);
    float* shu    = (float*)(smem + UOFF2);
    float* shwred = (float*)(smem + WREDO);
    float* shy    = (float*)(smem + YO);
    float* shpart = (float*)(smem + PARTO);

    const int tid = threadIdx.x;
    const int w   = tid >> 5;
    const int l   = tid & 31;
    const int rg  = w >> 2;              // 0..1 row group (m16)
    const int cq  = w & 3;               // 0..3 col quad (n16 per gate)
    const int row0 = blockIdx.x * ROWS;

    for (int i = tid; i < GD; i += NTHR) { shv[i] = g_v[i]; shu[i] = g_u[i]; }
    for (int i = tid; i < HD; i += NTHR) shwred[i] = W_red[i];
    if (tid < ROWS) shy[tid] = finalx[row0 + tid];
    const float bred = __ldg(b_red);

    // ---- h0 = enc @ W_enc + b_enc ([32,512]@[512,256], scalar) ----
    {
        float* senc = (float*)(smem + BBUF);          // [32][32]
        float* swe  = (float*)(smem + BBUF + 4096);   // [32][256]
        float a[4][8];
        #pragma unroll
        for (int r = 0; r < 4; ++r)
            #pragma unroll
            for (int c = 0; c < 8; ++c) a[r][c] = 0.f;

        for (int k0 = 0; k0 < ENCD; k0 += 32) {
            __syncthreads();
            { int r = tid >> 3, c4 = (tid & 7) * 4;
              *(float4*)(senc + r * 32 + c4) =
                  *(const float4*)(enc + (size_t)(row0 + r) * ENCD + k0 + c4); }
            #pragma unroll
            for (int s = 0; s < 8; ++s) {
                int slot = tid + s * NTHR;
                int kk = slot >> 6, c4 = (slot & 63) * 4;
                *(float4*)(swe + kk * 256 + c4) =
                    *(const float4*)(W_enc + (size_t)(k0 + kk) * HD + c4);
            }
            __syncthreads();
            #pragma unroll
            for (int kk = 0; kk < 32; ++kk) {
                float av[4];
                #pragma unroll
                for (int r = 0; r < 4; ++r) av[r] = senc[(4 * w + r) * 32 + kk];
                float4 b0 = *(const float4*)(swe + kk * 256 + l * 8);
                float4 b1 = *(const float4*)(swe + kk * 256 + l * 8 + 4);
                #pragma unroll
                for (int r = 0; r < 4; ++r) {
                    a[r][0] += av[r] * b0.x; a[r][1] += av[r] * b0.y;
                    a[r][2] += av[r] * b0.z; a[r][3] += av[r] * b0.w;
                    a[r][4] += av[r] * b1.x; a[r][5] += av[r] * b1.y;
                    a[r][6] += av[r] * b1.z; a[r][7] += av[r] * b1.w;
                }
            }
        }
        __syncthreads();
        #pragma unroll
        for (int r = 0; r < 4; ++r)
            #pragma unroll
            for (int c = 0; c < 8; ++c) {
                float val = a[r][c] + __ldg(b_enc + l * 8 + c);
                __nv_bfloat16 hi = __float2bfloat16(val);
                int off = (4 * w + r) * HROWB + (l * 8 + c) * 2;
                *(unsigned short*)(smem + AHI + off) = __bfloat16_as_ushort(hi);
                *(unsigned short*)(smem + ALO + off) = __bfloat16_as_ushort(
                    __float2bfloat16(val - __bfloat162float(hi)));
            }
    }
    __syncthreads();

    // prologue: stage chunk 0 into parity buffer 0
    #pragma unroll
    for (int i = 0; i < 8; ++i)
        cp16(smem + BBUF + tid * 128 + i * 16, g_wimg + tid * 64 + i * 8);
    asm volatile("cp.async.commit_group;" ::: "memory");

    const unsigned smem_sh = (unsigned)__cvta_generic_to_shared(smem);
    const unsigned a_base = smem_sh + AHI + (rg * 16 + (l & 15)) * HROWB + (l >> 4) * 16;
    const int rb = (l & 7) + ((l >> 4) << 3);        // B lane row within n16
    const int r0 = rg * 16 + (l >> 2);
    const int r1 = r0 + 8;

    float cst[4][8];
    #pragma unroll
    for (int p = 0; p < 4; ++p)
        #pragma unroll
        for (int c = 0; c < 8; ++c) cst[p][c] = 0.f;
    unsigned hstash[4][8];

    #pragma unroll 1
    for (int t = 0; t < TSTEPS; ++t) {
        float yd0 = 0.f, yd1 = 0.f;

        #pragma unroll
        for (int p = 0; p < 4; ++p) {
            float acc[4][2][4];
            #pragma unroll
            for (int g = 0; g < 4; ++g)
                #pragma unroll
                for (int j = 0; j < 2; ++j) {
                    acc[g][j][0] = 0.f; acc[g][j][1] = 0.f;
                    acc[g][j][2] = 0.f; acc[g][j][3] = 0.f;
                }

            #pragma unroll
            for (int kc = 0; kc < 8; ++kc) {
                int c = p * 8 + kc;
                {   // stage chunk c+1 into parity (c+1)&1
                    int nc = (c + 1) & 31;
                    const unsigned short* src = g_wimg + nc * 16384 + tid * 64;
                    char* dst = smem + BBUF + ((c + 1) & 1) * 32768 + tid * 128;
                    #pragma unroll
                    for (int i = 0; i < 8; ++i) cp16(dst + i * 16, src + i * 8);
                    asm volatile("cp.async.commit_group;" ::: "memory");
                }
                asm volatile("cp.async.wait_group 1;" ::: "memory");
                __syncthreads();                     // chunk c visible

                unsigned bbase = smem_sh + BBUF + (unsigned)((c & 1) * 32768);
                #pragma unroll
                for (int s = 0; s < 2; ++s) {
                    unsigned ahi[4], alo[4];
                    unsigned ak = (unsigned)(kc * 64 + s * 32);
                    ldm_x4(ahi, a_base + ak);
                    ldm_x4(alo, a_base + (ALO - AHI) + ak);
                    int khalf = (l >> 3) & 1;
                    #pragma unroll
                    for (int g = 0; g < 4; ++g) {
                        int rbr = g * 64 + cq * 16 + rb;
                        unsigned rowa = bbase + (unsigned)(rbr * 128);
                        int uh = s * 2 + khalf;          // hi unit
                        int ul = 4 + s * 2 + khalf;      // lo unit
                        unsigned bhi[4], blo[4];
                        ldm_x4(bhi, rowa + (unsigned)(((uh ^ (rbr & 7)) << 4)));
                        ldm_x4(blo, rowa + (unsigned)(((ul ^ (rbr & 7)) << 4)));
                        mma_bf16(acc[g][0], ahi, bhi + 0);
                        mma_bf16(acc[g][1], ahi, bhi + 2);
                        mma_bf16(acc[g][0], ahi, blo + 0);
                        mma_bf16(acc[g][1], ahi, blo + 2);
                        mma_bf16(acc[g][0], alo, bhi + 0);
                        mma_bf16(acc[g][1], alo, bhi + 2);
                    }
                }
                __syncthreads();                     // buffer reuse fence
            }
            EPI(p);                                  // regs only; A untouched
        }

        // ---- writeback h' (all A reads finished at pass3 kc7 barrier) ----
        #pragma unroll
        for (int p = 0; p < 4; ++p)
            #pragma unroll
            for (int j = 0; j < 2; ++j)
                #pragma unroll
                for (int cp = 0; cp < 2; ++cp)
                    #pragma unroll
                    for (int rh = 0; rh < 2; ++rh) {
                        int ci = j * 4 + cp * 2 + rh;
                        int hcol = p * 64 + cq * 16 + j * 8 + (l & 3) * 2 + cp;
                        int r = (rh ? r1 : r0);
                        unsigned pk = hstash[p][ci];
                        int off = r * HROWB + hcol * 2;
                        *(unsigned short*)(smem + AHI + off) = (unsigned short)pk;
                        *(unsigned short*)(smem + ALO + off) = (unsigned short)(pk >> 16);
                    }

        // ---- y = h' @ w_red + b_red ----
        yd0 += __shfl_xor_sync(0xffffffffu, yd0, 1);
        yd0 += __shfl_xor_sync(0xffffffffu, yd0, 2);
        yd1 += __shfl_xor_sync(0xffffffffu, yd1, 1);
        yd1 += __shfl_xor_sync(0xffffffffu, yd1, 2);
        if ((l & 3) == 0) {
            shpart[r0 * 4 + cq] = yd0;
            shpart[r1 * 4 + cq] = yd1;
        }
        __syncthreads();
        if (tid < ROWS) {
            float y = shpart[tid * 4] + shpart[tid * 4 + 1]
                    + shpart[tid * 4 + 2] + shpart[tid * 4 + 3] + bred;
            shy[tid] = y;
            out[(size_t)(row0 + tid) * TSTEPS + t] = y;
        }
        // next step's first post-wait __syncthreads publishes shy + A image
    }
    asm volatile("cp.async.wait_group 0;" ::: "memory");
}

extern "C" void kernel_launch(void* const* d_in, const int* in_sizes, int n_in,
                              void* d_out, int out_size) {
    const float* enc    = (const float*)d_in[0];
    const float* finalx = (const float*)d_in[1];
    const float* W_emb  = (const float*)d_in[2];
    const float* b_emb  = (const float*)d_in[3];
    const float* W_enc  = (const float*)d_in[4];
    const float* b_enc  = (const float*)d_in[5];
    const float* W_k    = (const float*)d_in[6];
    const float* W_r    = (const float*)d_in[7];
    const float* b_lstm = (const float*)d_in[8];
    const float* W_red  = (const float*)d_in[9];
    const float* b_red  = (const float*)d_in[10];
    float* out = (float*)d_out;

    cudaFuncSetAttribute(lstm_decode_kernel,
                         cudaFuncAttributeMaxDynamicSharedMemorySize, SMEMSZ);

    precompute_vu_kernel<<<8, 128>>>(W_emb, b_emb, W_k, b_lstm);
    precompute_wimg_kernel<<<256, 256>>>(W_r);
    lstm_decode_kernel<<<BATCH / ROWS, NTHR, SMEMSZ>>>(
        enc, finalx, W_enc, b_enc, W_red, b_red, out);
}

// round 17
// speedup vs baseline: 2.4648x; 2.4648x over previous
#include <cuda_runtime.h>
#include <cuda_bf16.h>
#include <math.h>

#define BATCH   16384
#define ENCD    512
#define HD      256
#define GD      1024
#define TSTEPS  64
#define MROWS   64
#define NTHR    512
#define HROW    264     // padded h row length (bf16 elems)
#define HROWB   528     // bytes
#define WROWB   80      // padded W buffer row bytes
#define CHUNKB  40960   // one W chunk in smem: hi 20480 + lo 20480

#define HBYTES  33792   // 64*264*2
#define WBOFF   135168  // 4*HBYTES
#define WBUFSZ  20480
#define VOFF    217088
#define UOFF    221184
#define WREDOFF 225280
#define YOFF    226304
#define PARTOFF 226560
#define MBAR    227584  // 2 mbarriers (8B each)
#define SMEMSZ  227648

// v[j] = W_emb @ W_k[:,j] ; u[j] = b_emb @ W_k[:,j] + b_lstm[j]
__device__ float g_v[GD];
__device__ float g_u[GD];
// W image in global, byte-identical to the staged SMEM chunk layout:
// chunk c (0..31, c = p*8+kc): [hi: 256 rows x 80B][lo: 256 rows x 80B]
// row rr (n' = p*256+rr -> n = g*256+p*64+w64), bytes [k*2] = element k (0..31)
__device__ __align__(16) unsigned short g_wimg[32 * 20480];

__global__ void precompute_vu_kernel(const float* __restrict__ W_emb,
                                     const float* __restrict__ b_emb,
                                     const float* __restrict__ W_k,
                                     const float* __restrict__ b_lstm) {
    int j = blockIdx.x * blockDim.x + threadIdx.x;
    if (j < GD) {
        float v = 0.f, u = 0.f;
        #pragma unroll
        for (int d = 0; d < 32; ++d) {
            float wk = W_k[d * GD + j];
            v += W_emb[d] * wk;
            u += b_emb[d] * wk;
        }
        g_v[j] = v;
        g_u[j] = u + b_lstm[j];
    }
}

__global__ void precompute_wimg_kernel(const float* __restrict__ W_r) {
    int idx = blockIdx.x * blockDim.x + threadIdx.x;   // 32*256*32 = 262144
    if (idx >= 32 * 256 * 32) return;
    int k  = idx & 31;                 // element within chunk row
    int rr = (idx >> 5) & 255;         // chunk-local n' row
    int c  = idx >> 13;                // chunk 0..31
    int p  = c >> 3, kc = c & 7;
    int g  = rr >> 6, w64 = rr & 63;
    int n  = g * 256 + p * 64 + w64;
    int kglob = kc * 32 + k;
    float val = W_r[(size_t)kglob * GD + n];
    __nv_bfloat16 hi = __float2bfloat16(val);
    __nv_bfloat16 lo = __float2bfloat16(val - __bfloat162float(hi));
    // ushort units: chunk base c*20480; row rr*40; hi at +k, lo at +10240
    g_wimg[c * 20480 + rr * 40 + k]         = __bfloat16_as_ushort(hi);
    g_wimg[c * 20480 + 10240 + rr * 40 + k] = __bfloat16_as_ushort(lo);
}

__device__ __forceinline__ float sigmoidf_(float x) {
    return __fdividef(1.f, 1.f + __expf(-x));
}
__device__ __forceinline__ float tanh_fast(float x) {
    float e = __expf(-2.f * x);
    return __fdividef(1.f - e, 1.f + e);
}
__device__ __forceinline__ void ldm_x4(unsigned* r, unsigned addr) {
    asm volatile("ldmatrix.sync.aligned.m8n8.x4.shared.b16 {%0,%1,%2,%3}, [%4];"
                 : "=r"(r[0]), "=r"(r[1]), "=r"(r[2]), "=r"(r[3]) : "r"(addr));
}
__device__ __forceinline__ void mma_bf16(float* d, const unsigned* a, const unsigned* b) {
    asm volatile("mma.sync.aligned.m16n8k16.row.col.f32.bf16.bf16.f32 "
                 "{%0,%1,%2,%3}, {%4,%5,%6,%7}, {%8,%9}, {%0,%1,%2,%3};"
                 : "+f"(d[0]), "+f"(d[1]), "+f"(d[2]), "+f"(d[3])
                 : "r"(a[0]), "r"(a[1]), "r"(a[2]), "r"(a[3]), "r"(b[0]), "r"(b[1]));
}
__device__ __forceinline__ void mbar_wait(unsigned a, unsigned par) {
    asm volatile(
        "{\n.reg .pred P;\nW%=:\n"
        "mbarrier.try_wait.parity.acquire.cta.shared::cta.b64 P, [%0], %1, 0x989680;\n"
        "@P bra D%=;\nbra W%=;\nD%=:\n}"
        :: "r"(a), "r"(par) : "memory");
}

__global__ void __launch_bounds__(NTHR, 1)
lstm_decode_kernel(const float* __restrict__ enc,
                   const float* __restrict__ finalx,
                   const float* __restrict__ W_enc,
                   const float* __restrict__ b_enc,
                   const float* __restrict__ W_red,
                   const float* __restrict__ b_red,
                   float* __restrict__ out)
{
    extern __shared__ char smem[];
    float* shv    = (float*)(smem + VOFF);
    float* shu    = (float*)(smem + UOFF);
    float* shwred = (float*)(smem + WREDOFF);
    float* shy    = (float*)(smem + YOFF);
    float* shpart = (float*)(smem + PARTOFF);

    const int tid = threadIdx.x;
    const int w   = tid >> 5;
    const int l   = tid & 31;
    const int rg  = w >> 2;
    const int q   = w & 3;
    const int row0 = blockIdx.x * MROWS;
    const unsigned smem_sh = (unsigned)__cvta_generic_to_shared(smem);

    for (int i = tid; i < GD; i += NTHR) { shv[i] = g_v[i]; shu[i] = g_u[i]; }
    for (int i = tid; i < HD; i += NTHR) shwred[i] = W_red[i];
    if (tid < MROWS) shy[tid] = finalx[row0 + tid];
    const float bred = __ldg(b_red);

    // ---- h0 = enc @ W_enc + b_enc  ([64,512]@[512,256], scalar fp32) ----
    {
        float* senc = (float*)(smem + WBOFF);
        float* swe  = (float*)(smem + WBOFF + 8192);
        float a[4][8];
        #pragma unroll
        for (int r = 0; r < 4; ++r)
            #pragma unroll
            for (int c = 0; c < 8; ++c) a[r][c] = 0.f;

        for (int k0 = 0; k0 < ENCD; k0 += 32) {
            __syncthreads();
            { int r = tid >> 3, c4 = (tid & 7) * 4;
              *(float4*)(senc + r * 32 + c4) =
                  *(const float4*)(enc + (size_t)(row0 + r) * ENCD + k0 + c4); }
            #pragma unroll
            for (int s = 0; s < 4; ++s) {
                int slot = tid + s * NTHR;
                int kk = slot >> 6, c4 = (slot & 63) * 4;
                *(float4*)(swe + kk * 256 + c4) =
                    *(const float4*)(W_enc + (size_t)(k0 + kk) * HD + c4);
            }
            __syncthreads();
            #pragma unroll
            for (int kk = 0; kk < 32; ++kk) {
                float av[4];
                #pragma unroll
                for (int r = 0; r < 4; ++r) av[r] = senc[(4 * w + r) * 32 + kk];
                float4 b0 = *(const float4*)(swe + kk * 256 + l * 8);
                float4 b1 = *(const float4*)(swe + kk * 256 + l * 8 + 4);
                #pragma unroll
                for (int r = 0; r < 4; ++r) {
                    a[r][0] += av[r] * b0.x; a[r][1] += av[r] * b0.y;
                    a[r][2] += av[r] * b0.z; a[r][3] += av[r] * b0.w;
                    a[r][4] += av[r] * b1.x; a[r][5] += av[r] * b1.y;
                    a[r][6] += av[r] * b1.z; a[r][7] += av[r] * b1.w;
                }
            }
        }
        __syncthreads();
        __nv_bfloat16* hh = (__nv_bfloat16*)(smem);
        __nv_bfloat16* hl = (__nv_bfloat16*)(smem + HBYTES);
        #pragma unroll
        for (int r = 0; r < 4; ++r)
            #pragma unroll
            for (int c = 0; c < 8; ++c) {
                float val = a[r][c] + __ldg(b_enc + l * 8 + c);
                __nv_bfloat16 hi = __float2bfloat16(val);
                hh[(4 * w + r) * HROW + l * 8 + c] = hi;
                hl[(4 * w + r) * HROW + l * 8 + c] =
                    __float2bfloat16(val - __bfloat162float(hi));
            }
    }

    // ---- mbarrier init + prologue bulk: chunk 0 -> buf 0 ----
    if (tid == 0) {
        asm volatile("mbarrier.init.shared.b64 [%0], 1;" :: "r"(smem_sh + MBAR) : "memory");
        asm volatile("mbarrier.init.shared.b64 [%0], 1;" :: "r"(smem_sh + MBAR + 8) : "memory");
    }
    __syncthreads();   // mbar init visible CTA-wide (h0 A-image published by loop-top sync)
    if (tid == 0) {
        asm volatile("mbarrier.arrive.expect_tx.shared.b64 _, [%0], %1;"
                     :: "r"(smem_sh + MBAR), "r"((unsigned)CHUNKB) : "memory");
        asm volatile("cp.async.bulk.shared::cluster.global.mbarrier::complete_tx::bytes "
                     "[%0], [%1], %2, [%3];"
                     :: "r"(smem_sh + WBOFF), "l"((const char*)g_wimg),
                        "r"((unsigned)CHUNKB), "r"(smem_sh + MBAR) : "memory");
    }

    const unsigned a_off = (rg * 16 + (l & 15)) * HROWB + (l >> 4) * 16;
    const unsigned b_off = (q * 16 + (l & 7) + ((l >> 4) << 3)) * WROWB + ((l >> 3) & 1) * 16;
    const int r0 = rg * 16 + (l >> 2);
    const int r1 = r0 + 8;

    float cst[4][2][2][2];
    #pragma unroll
    for (int p = 0; p < 4; ++p)
        #pragma unroll
        for (int j = 0; j < 2; ++j) {
            cst[p][j][0][0] = 0.f; cst[p][j][0][1] = 0.f;
            cst[p][j][1][0] = 0.f; cst[p][j][1][1] = 0.f;
        }

    #pragma unroll 1
    for (int t = 0; t < TSTEPS; ++t) {
        const unsigned hcur = smem_sh + (unsigned)(t & 1) * (2 * HBYTES);
        const unsigned ahib = hcur + a_off;
        const unsigned alob = hcur + HBYTES + a_off;
        __nv_bfloat16* hn_hi = (__nv_bfloat16*)(smem + ((t + 1) & 1) * (2 * HBYTES));
        __nv_bfloat16* hn_lo = (__nv_bfloat16*)(smem + ((t + 1) & 1) * (2 * HBYTES) + HBYTES);
        float yd0 = 0.f, yd1 = 0.f;

        #pragma unroll
        for (int p = 0; p < 4; ++p) {
            float acc[4][2][4];
            #pragma unroll
            for (int g = 0; g < 4; ++g)
                #pragma unroll
                for (int j = 0; j < 2; ++j) {
                    acc[g][j][0] = 0.f; acc[g][j][1] = 0.f;
                    acc[g][j][2] = 0.f; acc[g][j][3] = 0.f;
                }

            #pragma unroll
            for (int kc = 0; kc < 8; ++kc) {
                // all threads finished chunk cg-1 (whose buffer we now refill)
                __syncthreads();
                int cg = (t * 4 + p) * 8 + kc;         // global chunk counter
                if (tid == 0 && cg < TSTEPS * 32 - 1) {
                    int par = (cg + 1) & 1;
                    unsigned mb = smem_sh + MBAR + (unsigned)(par * 8);
                    asm volatile("mbarrier.arrive.expect_tx.shared.b64 _, [%0], %1;"
                                 :: "r"(mb), "r"((unsigned)CHUNKB) : "memory");
                    asm volatile("cp.async.bulk.shared::cluster.global.mbarrier::complete_tx::bytes "
                                 "[%0], [%1], %2, [%3];"
                                 :: "r"(smem_sh + WBOFF + (unsigned)(par * CHUNKB)),
                                    "l"((const char*)g_wimg + ((cg + 1) & 31) * CHUNKB),
                                    "r"((unsigned)CHUNKB), "r"(mb) : "memory");
                }
                int parc = cg & 1;
                mbar_wait(smem_sh + MBAR + (unsigned)(parc * 8),
                          (unsigned)((cg >> 1) & 1));

                unsigned wb = smem_sh + WBOFF + (unsigned)(parc * CHUNKB);
                #pragma unroll
                for (int s = 0; s < 2; ++s) {
                    unsigned ahi[4], alo[4];
                    unsigned ak = (unsigned)(kc * 64 + s * 32);
                    ldm_x4(ahi, ahib + ak);
                    ldm_x4(alo, alob + ak);
                    #pragma unroll
                    for (int g = 0; g < 4; ++g) {
                        unsigned bhi[4], blo[4];
                        unsigned baddr = wb + (unsigned)(g * 64 * WROWB) + b_off + s * 32;
                        ldm_x4(bhi, baddr);
                        ldm_x4(blo, baddr + WBUFSZ);
                        mma_bf16(acc[g][0], ahi, bhi + 0);
                        mma_bf16(acc[g][1], ahi, bhi + 2);
                        mma_bf16(acc[g][0], ahi, blo + 0);
                        mma_bf16(acc[g][1], ahi, blo + 2);
                        mma_bf16(acc[g][0], alo, bhi + 0);
                        mma_bf16(acc[g][1], alo, bhi + 2);
                    }
                }
            }

            // ---- epilogue for pass p (warp-local gates) ----
            float yp0 = shy[r0], yp1 = shy[r1];
            #pragma unroll
            for (int j = 0; j < 2; ++j)
                #pragma unroll
                for (int cp = 0; cp < 2; ++cp) {
                    int hcol = p * 64 + q * 16 + j * 8 + (l & 3) * 2 + cp;
                    float vi = shv[hcol],          ui = shu[hcol];
                    float vf = shv[HD + hcol],     uf = shu[HD + hcol];
                    float vc = shv[2 * HD + hcol], uc = shu[2 * HD + hcol];
                    float vo = shv[3 * HD + hcol], uo = shu[3 * HD + hcol];
                    float wr = shwred[hcol];
                    #pragma unroll
                    for (int rh = 0; rh < 2; ++rh) {
                        float yy = rh ? yp1 : yp0;
                        int di = rh * 2 + cp;
                        float gi = acc[0][j][di] + yy * vi + ui;
                        float gf = acc[1][j][di] + yy * vf + uf;
                        float gc = acc[2][j][di] + yy * vc + uc;
                        float go = acc[3][j][di] + yy * vo + uo;
                        float cn = sigmoidf_(gf) * cst[p][j][rh][cp]
                                 + sigmoidf_(gi) * tanh_fast(gc);
                        float hn = sigmoidf_(go) * tanh_fast(cn);
                        cst[p][j][rh][cp] = cn;
                        int rr = rh ? r1 : r0;
                        __nv_bfloat16 hb = __float2bfloat16(hn);
                        hn_hi[rr * HROW + hcol] = hb;
                        hn_lo[rr * HROW + hcol] =
                            __float2bfloat16(hn - __bfloat162float(hb));
                        if (rh) yd1 += hn * wr; else yd0 += hn * wr;
                    }
                }
        }

        // ---- y = h_new @ w_red + b_red ----
        yd0 += __shfl_xor_sync(0xffffffffu, yd0, 1);
        yd0 += __shfl_xor_sync(0xffffffffu, yd0, 2);
        yd1 += __shfl_xor_sync(0xffffffffu, yd1, 1);
        yd1 += __shfl_xor_sync(0xffffffffu, yd1, 2);
        if ((l & 3) == 0) {
            shpart[r0 * 4 + q] = yd0;
            shpart[r1 * 4 + q] = yd1;
        }
        __syncthreads();
        if (tid < MROWS) {
            float y = shpart[tid * 4] + shpart[tid * 4 + 1]
                    + shpart[tid * 4 + 2] + shpart[tid * 4 + 3] + bred;
            shy[tid] = y;
            out[(size_t)(row0 + tid) * TSTEPS + t] = y;
        }
        // next step's first chunk __syncthreads publishes shy + new A image
    }
}

extern "C" void kernel_launch(void* const* d_in, const int* in_sizes, int n_in,
                              void* d_out, int out_size) {
    const float* enc    = (const float*)d_in[0];
    const float* finalx = (const float*)d_in[1];
    const float* W_emb  = (const float*)d_in[2];
    const float* b_emb  = (const float*)d_in[3];
    const float* W_enc  = (const float*)d_in[4];
    const float* b_enc  = (const float*)d_in[5];
    const float* W_k    = (const float*)d_in[6];
    const float* W_r    = (const float*)d_in[7];
    const float* b_lstm = (const float*)d_in[8];
    const float* W_red  = (const float*)d_in[9];
    const float* b_red  = (const float*)d_in[10];
    float* out = (float*)d_out;

    cudaFuncSetAttribute(lstm_decode_kernel,
                         cudaFuncAttributeMaxDynamicSharedMemorySize, SMEMSZ);

    precompute_vu_kernel<<<8, 128>>>(W_emb, b_emb, W_k, b_lstm);
    precompute_wimg_kernel<<<1024, 256>>>(W_r);
    lstm_decode_kernel<<<BATCH / MROWS, NTHR, SMEMSZ>>>(
        enc, finalx, W_enc, b_enc, W_red, b_red, out);
}